// round 1
// baseline (speedup 1.0000x reference)
#include <cuda_runtime.h>
#include <cuda_bf16.h>

// Problem constants (fixed by the reference)
#define BB      2
#define XX      200
#define YY      200
#define ZZ      16      // == HEIGHT, so h = 1
#define CC      17
#define CHOOSE  4000
#define EMPTY_LABEL 16

#define TPB 256
#define BLOCKS_PER_Z ((CHOOSE + TPB - 1) / TPB)   // 16
#define GRID (BB * ZZ * BLOCKS_PER_Z)             // 512

// Scratch (allocation-free: device globals)
__device__ float g_llog[BB][ZZ][CHOOSE];   // log(p_label + 0.001), 0 for invalid
__device__ int   g_counts[BB][ZZ];
__device__ float g_loss[BB];

// ---------------------------------------------------------------------------
__global__ void k0_zero() {
    int t = threadIdx.x;
    if (t < BB * ZZ) ((int*)g_counts)[t] = 0;
    if (t < BB)      g_loss[t] = 0.0f;
}

// ---------------------------------------------------------------------------
// One thread per (b, z, m) voxel: gather label + 17 logits, compute
// log(softmax[label] + 0.001). Store 0 for invalid (smoothL1(w*0)==0, exact).
__global__ void __launch_bounds__(TPB)
k1_gather(const float* __restrict__ preds,
          const int*   __restrict__ labels,
          const int*   __restrict__ sel) {
    int bid = blockIdx.x;
    int b = bid / (ZZ * BLOCKS_PER_Z);
    int z = (bid / BLOCKS_PER_Z) % ZZ;
    int m = (bid % BLOCKS_PER_Z) * TPB + threadIdx.x;

    bool valid = false;
    if (m < CHOOSE) {
        int sbase = (b * CHOOSE + m) * 2;
        int x = sel[sbase];
        int y = sel[sbase + 1];
        int col = (b * XX + x) * YY + y;          // fits in int (< 80000)
        int lab = labels[col * ZZ + z];
        valid = (lab != EMPTY_LABEL);
        float ll = 0.0f;
        if (valid) {
            const float* __restrict__ p = preds + ((col * ZZ + z) * CC);
            float v[CC];
            float mx = -1e30f;
            float vlab = 0.0f;
            #pragma unroll
            for (int c = 0; c < CC; c++) {
                v[c] = p[c];
                mx = fmaxf(mx, v[c]);
                if (c == lab) vlab = v[c];        // SEL, no dynamic indexing
            }
            float s = 0.0f;
            #pragma unroll
            for (int c = 0; c < CC; c++) s += __expf(v[c] - mx);
            float plab = __expf(vlab - mx) / s;
            ll = logf(plab + 0.001f);
        }
        g_llog[b][z][m] = valid ? ll : 0.0f;
    }

    // count valid per (b,z): ballot -> shared -> one global atomic per block
    unsigned bal = __ballot_sync(0xffffffffu, valid);
    __shared__ int scnt;
    if (threadIdx.x == 0) scnt = 0;
    __syncthreads();
    if ((threadIdx.x & 31) == 0) atomicAdd(&scnt, __popc(bal));
    __syncthreads();
    if (threadIdx.x == 0) atomicAdd(&g_counts[b][z], scnt);
}

// ---------------------------------------------------------------------------
// Weighted smooth-L1 + per-batch reduction. Weight recomputed inline from the
// 32 counts (cheap; avoids an extra kernel).
__global__ void __launch_bounds__(TPB)
k2_reduce() {
    int bid = blockIdx.x;
    int b = bid / (ZZ * BLOCKS_PER_Z);
    int z = (bid / BLOCKS_PER_Z) % ZZ;
    int m = (bid % BLOCKS_PER_Z) * TPB + threadIdx.x;

    __shared__ float sw;
    if (threadIdx.x == 0) {
        int maxc = 0;
        #pragma unroll
        for (int zz = 0; zz < ZZ; zz++) maxc = max(maxc, g_counts[b][zz]);
        float maxcf = fmaxf((float)maxc, 1.0f);
        int c = g_counts[b][z];
        // MAX_W * ratio^(c/maxc), ratio = MIN_W/MAX_W = 1/3
        const float LOG_RATIO = -1.0986122886681098f;  // ln(1/3)
        sw = (c > 0) ? 3.0f * __expf(((float)c / maxcf) * LOG_RATIO) : 0.0f;
    }
    __syncthreads();
    float w = sw;

    float val = 0.0f;
    if (m < CHOOSE) {
        float wl = w * g_llog[b][z][m];
        float ax = fabsf(wl);
        val = (ax < 1.0f) ? 0.5f * wl * wl : (ax - 0.5f);
    }

    // block reduction
    #pragma unroll
    for (int off = 16; off > 0; off >>= 1)
        val += __shfl_down_sync(0xffffffffu, val, off);
    __shared__ float swarp[TPB / 32];
    int wid = threadIdx.x >> 5;
    int lid = threadIdx.x & 31;
    if (lid == 0) swarp[wid] = val;
    __syncthreads();
    if (wid == 0) {
        float v = (lid < TPB / 32) ? swarp[lid] : 0.0f;
        #pragma unroll
        for (int off = 4; off > 0; off >>= 1)
            v += __shfl_down_sync(0xffffffffu, v, off);
        if (lid == 0) atomicAdd(&g_loss[b], v);
    }
}

// ---------------------------------------------------------------------------
__global__ void k3_final(float* __restrict__ out) {
    float acc = 0.0f;
    #pragma unroll
    for (int b = 0; b < BB; b++) {
        int n = 0;
        #pragma unroll
        for (int zz = 0; zz < ZZ; zz++) n += g_counts[b][zz];
        float nf = fmaxf((float)n, 1.0f);
        acc += g_loss[b] / nf;
    }
    out[0] = acc / (float)BB;
}

// ---------------------------------------------------------------------------
extern "C" void kernel_launch(void* const* d_in, const int* in_sizes, int n_in,
                              void* d_out, int out_size) {
    // Resolve inputs by element count (defensive against ordering)
    const float* preds  = nullptr;
    const int*   labels = nullptr;
    const int*   sel    = nullptr;
    for (int i = 0; i < n_in; i++) {
        if (in_sizes[i] == BB * XX * YY * ZZ * CC)      preds  = (const float*)d_in[i];
        else if (in_sizes[i] == BB * XX * YY * ZZ)      labels = (const int*)d_in[i];
        else if (in_sizes[i] == BB * CHOOSE * 2)        sel    = (const int*)d_in[i];
    }
    float* out = (float*)d_out;

    k0_zero<<<1, 64>>>();
    k1_gather<<<GRID, TPB>>>(preds, labels, sel);
    k2_reduce<<<GRID, TPB>>>();
    k3_final<<<1, 1>>>(out);
}